// round 4
// baseline (speedup 1.0000x reference)
#include <cuda_runtime.h>
#include <cuda_fp16.h>
#include <cstdint>
#include <cstddef>

// out[h,n,m] = LeakyReLU_{0.2}( sum_d z0[n,d]*z1[m,d]*W[h,d] + bias[h] )
// N=M=1024, D=256, H=128, fp32 in/out.
//
//  prep_z1 : z1   -> g_z1h  fp16, layout [mtile(8)][khalf(2)][128r x 256B], swizzle baked
//  prep_y  : z0,W -> g_Yh   fp16(z0*W[h]), [h(128)][ns(4)][khalf(2)][256r x 256B]
//  main    : CTA=(h, 256-row n-supertile); B tile (Yh, 128KB) loaded once;
//            A (z1) double-buffered 32KB k-halves; 64n x 64m warp tiles.

#define NT 256

static constexpr int SM_A0 = 0;         // 32KB
static constexpr int SM_A1 = 32768;     // 32KB
static constexpr int SM_B  = 65536;     // 128KB (two k-halves of 64KB)
static constexpr int SMEM_BYTES = 196608;

__device__ uint4 g_Yh[128 * 4 * 2 * 4096];   // 64 MB
__device__ uint4 g_z1h[8 * 2 * 2048];        // 512 KB

__device__ __forceinline__ uint32_t smem_u32(const void* p) {
    uint32_t a;
    asm("{ .reg .u64 t; cvta.to.shared.u64 t, %1; cvt.u32.u64 %0, t; }" : "=r"(a) : "l"(p));
    return a;
}

#define CP16(saddr, gptr)                                                     \
    asm volatile("cp.async.cg.shared.global [%0], [%1], 16;"                  \
                 :: "r"(saddr), "l"(gptr))
#define CP_COMMIT() asm volatile("cp.async.commit_group;" ::: "memory")
#define CP_WAIT(n)  asm volatile("cp.async.wait_group %0;" :: "n"(n) : "memory")

#define LDMATRIX_X4(r0, r1, r2, r3, addr)                                     \
    asm volatile("ldmatrix.sync.aligned.m8n8.x4.shared.b16 {%0,%1,%2,%3}, [%4];" \
                 : "=r"(r0), "=r"(r1), "=r"(r2), "=r"(r3) : "r"(addr))

#define MMA16816(c, a, b0, b1)                                                 \
    asm volatile("mma.sync.aligned.m16n8k16.row.col.f32.f16.f16.f32 "          \
                 "{%0,%1,%2,%3}, {%4,%5,%6,%7}, {%8,%9}, {%0,%1,%2,%3};"       \
                 : "+f"((c)[0]), "+f"((c)[1]), "+f"((c)[2]), "+f"((c)[3])      \
                 : "r"((a)[0]), "r"((a)[1]), "r"((a)[2]), "r"((a)[3]),         \
                   "r"(b0), "r"(b1))

// ---------------- pre-kernels ----------------
// Within a tile-half: chunk(r, c16) at r*256 + ((c16 ^ (r&7))*16.

__global__ void prep_z1_kernel(const float* __restrict__ z1) {
    const int wid = threadIdx.x >> 5, lid = threadIdx.x & 31;
    const int m = blockIdx.x * 8 + wid;
    const float4* src = reinterpret_cast<const float4*>(z1) + (size_t)m * 64 + lid * 2;
    float4 v0 = src[0], v1 = src[1];
    union { __half2 h2[4]; uint4 u; } pk;
    pk.h2[0] = __floats2half2_rn(v0.x, v0.y);
    pk.h2[1] = __floats2half2_rn(v0.z, v0.w);
    pk.h2[2] = __floats2half2_rn(v1.x, v1.y);
    pk.h2[3] = __floats2half2_rn(v1.z, v1.w);
    const int r = m & 127;
    g_z1h[((m >> 7) * 2 + (lid >> 4)) * 2048 + r * 16 + ((lid & 15) ^ (r & 7))] = pk.u;
}

__global__ void prep_y_kernel(const float* __restrict__ z0, const float* __restrict__ W) {
    const int wid = threadIdx.x >> 5, lid = threadIdx.x & 31;
    const int h = blockIdx.x >> 7;
    const int n = (blockIdx.x & 127) * 8 + wid;
    const float4* zsrc = reinterpret_cast<const float4*>(z0) + (size_t)n * 64 + lid * 2;
    const float4* wsrc = reinterpret_cast<const float4*>(W)  + (size_t)h * 64 + lid * 2;
    float4 v0 = zsrc[0], v1 = zsrc[1];
    float4 w0 = wsrc[0], w1 = wsrc[1];
    union { __half2 h2[4]; uint4 u; } pk;
    pk.h2[0] = __floats2half2_rn(v0.x * w0.x, v0.y * w0.y);
    pk.h2[1] = __floats2half2_rn(v0.z * w0.z, v0.w * w0.w);
    pk.h2[2] = __floats2half2_rn(v1.x * w1.x, v1.y * w1.y);
    pk.h2[3] = __floats2half2_rn(v1.z * w1.z, v1.w * w1.w);
    const int r = n & 255;
    g_Yh[(size_t)((h * 4 + (n >> 8)) * 2 + (lid >> 4)) * 4096 + r * 16 + ((lid & 15) ^ (r & 7))] = pk.u;
}

// ---------------- main kernel ----------------

__global__ void __launch_bounds__(NT, 1)
fc_main_kernel(const float* __restrict__ bias, float* __restrict__ out)
{
    extern __shared__ char smem[];
    const uint32_t smem_base = smem_u32(smem);
    const int tid = threadIdx.x;
    const int wid = tid >> 5;
    const int lid = tid & 31;

    const int h  = (int)(blockIdx.x & 127);
    const int ns = (int)(blockIdx.x >> 7);   // 0..3
    const int n0 = ns << 8;

    // Prologue: B (128KB), A(0), A(1)
    {
        const uint4* gB = g_Yh + (size_t)(h * 8 + ns * 2) * 4096;
        #pragma unroll
        for (int i = 0; i < 32; ++i)
            CP16(smem_base + SM_B + (uint32_t)((tid + i * 256) * 16), gB + tid + i * 256);
        CP_COMMIT();
        #pragma unroll
        for (int g = 0; g < 2; ++g) {
            const uint4* gA = g_z1h + (size_t)g * 2048;
            const uint32_t dst = smem_base + (uint32_t)(g * 32768);
            #pragma unroll
            for (int i = 0; i < 8; ++i)
                CP16(dst + (uint32_t)((tid + i * 256) * 16), gA + tid + i * 256);
            CP_COMMIT();
        }
    }

    const float bv = bias[h];

    // Warp tiling: 4(n) x 2(m); warp tile 64n x 64m.
    const int wn = wid >> 1;    // 0..3
    const int wm = wid & 1;     // 0..1

    const uint32_t e   = (uint32_t)(lid & 7);
    const uint32_t hi  = (uint32_t)(lid >> 4);
    const uint32_t row = (uint32_t)(lid & 15);

    uint32_t a_addr[4];   // operand A rows = n (Yh tile)
    #pragma unroll
    for (int mi = 0; mi < 4; ++mi)
        a_addr[mi] = smem_base + SM_B + (uint32_t)((wn * 64 + mi * 16 + row) * 256);
    uint32_t b_addr[4];   // operand B rows = m (z1 tile)
    #pragma unroll
    for (int u = 0; u < 4; ++u)
        b_addr[u] = smem_base + (uint32_t)((wm * 64 + u * 16 + row) * 256);

    float acc[4][8][4];
    #pragma unroll
    for (int mi = 0; mi < 4; ++mi)
        #pragma unroll
        for (int j = 0; j < 8; ++j)
            #pragma unroll
            for (int q = 0; q < 4; ++q) acc[mi][j][q] = 0.0f;

    #pragma unroll 1
    for (int g = 0; g < 16; ++g) {        // half-step: mt = g>>1, kh = g&1
        if (g < 15) { CP_WAIT(1); } else { CP_WAIT(0); }
        __syncthreads();                  // A(g) visible to all

        const uint32_t abuf  = (uint32_t)((g & 1) * 32768);
        const uint32_t khoff = (uint32_t)((g & 1) * 65536);

        #pragma unroll
        for (int ks = 0; ks < 8; ++ks) {
            const uint32_t coff = (uint32_t)((((uint32_t)ks * 2u + hi) ^ e) << 4);
            uint32_t fa[4][4], fb[4][4];
            #pragma unroll
            for (int mi = 0; mi < 4; ++mi)
                LDMATRIX_X4(fa[mi][0], fa[mi][1], fa[mi][2], fa[mi][3],
                            a_addr[mi] + khoff + coff);
            #pragma unroll
            for (int u = 0; u < 4; ++u)
                LDMATRIX_X4(fb[u][0], fb[u][1], fb[u][2], fb[u][3],
                            b_addr[u] + abuf + coff);
            #pragma unroll
            for (int mi = 0; mi < 4; ++mi)
                #pragma unroll
                for (int u = 0; u < 4; ++u) {
                    MMA16816(acc[mi][2 * u + 0], fa[mi], fb[u][0], fb[u][2]);
                    MMA16816(acc[mi][2 * u + 1], fa[mi], fb[u][1], fb[u][3]);
                }
        }

        if (g & 1) {
            // Epilogue for m-tile mt = g>>1
            const int m0 = (g >> 1) << 7;
            const int rr = lid >> 2;
            const int cc = (lid & 3) << 1;
            float* ob = out + (((size_t)h) << 20);
            #pragma unroll
            for (int mi = 0; mi < 4; ++mi) {
                const int ng = n0 + wn * 64 + mi * 16 + rr;
                #pragma unroll
                for (int j = 0; j < 8; ++j) {
                    const int mg = m0 + wm * 64 + j * 8 + cc;
                    float2 v0, v1;
                    v0.x = acc[mi][j][0] + bv; v0.y = acc[mi][j][1] + bv;
                    v1.x = acc[mi][j][2] + bv; v1.y = acc[mi][j][3] + bv;
                    v0.x = (v0.x >= 0.f) ? v0.x : 0.2f * v0.x;
                    v0.y = (v0.y >= 0.f) ? v0.y : 0.2f * v0.y;
                    v1.x = (v1.x >= 0.f) ? v1.x : 0.2f * v1.x;
                    v1.y = (v1.y >= 0.f) ? v1.y : 0.2f * v1.y;
                    __stcs(reinterpret_cast<float2*>(ob + (size_t)ng * 1024 + mg), v0);
                    __stcs(reinterpret_cast<float2*>(ob + (size_t)(ng + 8) * 1024 + mg), v1);
                    acc[mi][j][0] = acc[mi][j][1] = acc[mi][j][2] = acc[mi][j][3] = 0.0f;
                }
            }
        }

        __syncthreads();   // all readers done with buf(g&1) before refill
        if (g + 2 < 16) {
            const uint4* gA = g_z1h + (size_t)(g + 2) * 2048;
            const uint32_t dst = smem_base + (uint32_t)((g & 1) * 32768);
            #pragma unroll
            for (int i = 0; i < 8; ++i)
                CP16(dst + (uint32_t)((tid + i * 256) * 16), gA + tid + i * 256);
            CP_COMMIT();
        }
    }
}

extern "C" void kernel_launch(void* const* d_in, const int* in_sizes, int n_in,
                              void* d_out, int out_size) {
    const float* z0   = (const float*)d_in[0];   // (1, 1024, 256)
    const float* z1   = (const float*)d_in[1];   // (1, 1024, 256)
    const float* W    = (const float*)d_in[2];   // (128, 256)
    const float* bias = (const float*)d_in[3];   // (128,)
    float* out = (float*)d_out;                  // (1, 128, 1024, 1024)

    prep_z1_kernel<<<128, 256>>>(z1);
    prep_y_kernel<<<16384, 256>>>(z0, W);

    cudaFuncSetAttribute(fc_main_kernel, cudaFuncAttributeMaxDynamicSharedMemorySize, SMEM_BYTES);
    fc_main_kernel<<<512, NT, SMEM_BYTES>>>(bias, out);
}

// round 5
// speedup vs baseline: 1.1211x; 1.1211x over previous
#include <cuda_runtime.h>
#include <cuda_fp16.h>
#include <cstdint>
#include <cstddef>

// out[h,n,m] = LeakyReLU_{0.2}( sum_d z0[n,d]*z1[m,d]*W[h,d] + bias[h] )
// N=M=1024, D=256, H=128, fp32 in/out.
//
//  prep_z1 : z1   -> g_z1h  fp16  [ms(4)][kh(2)][256r x 256B] swizzle-baked
//  prep_y  : z0,W -> g_Yh   fp16  [h(128)][nt(8)][kh(2)][128r x 256B]
//  main    : CTA=(h, 128-row n-tile) covers all m. B tile 64KB loaded once;
//            A = 256m x 128k chunks (64KB) double-buffered.
//            16 warps (4n x 4m), warp tile 32n x 64m, 4 warps/SMSP.

#define NT 512

static constexpr int SM_A0 = 0;          // 64KB
static constexpr int SM_A1 = 65536;      // 64KB
static constexpr int SM_B  = 131072;     // 64KB (two 32KB k-half chunks)
static constexpr int SMEM_BYTES = 196608;

__device__ uint4 g_Yh[128 * 8 * 2 * 2048];   // 64 MB
__device__ uint4 g_z1h[4 * 2 * 4096];        // 512 KB

__device__ __forceinline__ uint32_t smem_u32(const void* p) {
    uint32_t a;
    asm("{ .reg .u64 t; cvta.to.shared.u64 t, %1; cvt.u32.u64 %0, t; }" : "=r"(a) : "l"(p));
    return a;
}

#define CP16(saddr, gptr)                                                     \
    asm volatile("cp.async.cg.shared.global [%0], [%1], 16;"                  \
                 :: "r"(saddr), "l"(gptr))
#define CP_COMMIT() asm volatile("cp.async.commit_group;" ::: "memory")
#define CP_WAIT(n)  asm volatile("cp.async.wait_group %0;" :: "n"(n) : "memory")

#define LDMATRIX_X4(r0, r1, r2, r3, addr)                                     \
    asm volatile("ldmatrix.sync.aligned.m8n8.x4.shared.b16 {%0,%1,%2,%3}, [%4];" \
                 : "=r"(r0), "=r"(r1), "=r"(r2), "=r"(r3) : "r"(addr))

#define MMA16816(c, a, b0, b1)                                                 \
    asm volatile("mma.sync.aligned.m16n8k16.row.col.f32.f16.f16.f32 "          \
                 "{%0,%1,%2,%3}, {%4,%5,%6,%7}, {%8,%9}, {%0,%1,%2,%3};"       \
                 : "+f"((c)[0]), "+f"((c)[1]), "+f"((c)[2]), "+f"((c)[3])      \
                 : "r"((a)[0]), "r"((a)[1]), "r"((a)[2]), "r"((a)[3]),         \
                   "r"(b0), "r"(b1))

// ---------------- pre-kernels ----------------
// Within a (rows x 256B) chunk: 16B unit (r, c) stored at r*16 + (c ^ (r&7)).

__global__ void prep_z1_kernel(const float* __restrict__ z1) {
    const int wid = threadIdx.x >> 5, lid = threadIdx.x & 31;
    const int m = blockIdx.x * 8 + wid;
    const float4* src = reinterpret_cast<const float4*>(z1) + (size_t)m * 64 + lid * 2;
    float4 v0 = src[0], v1 = src[1];
    union { __half2 h2[4]; uint4 u; } pk;
    pk.h2[0] = __floats2half2_rn(v0.x, v0.y);
    pk.h2[1] = __floats2half2_rn(v0.z, v0.w);
    pk.h2[2] = __floats2half2_rn(v1.x, v1.y);
    pk.h2[3] = __floats2half2_rn(v1.z, v1.w);
    const int r = m & 255;                   // row within 256-row supertile
    const int kh = lid >> 4, c = lid & 15;
    g_z1h[((m >> 8) * 2 + kh) * 4096 + r * 16 + (c ^ (r & 7))] = pk.u;
}

__global__ void prep_y_kernel(const float* __restrict__ z0, const float* __restrict__ W) {
    const int wid = threadIdx.x >> 5, lid = threadIdx.x & 31;
    const int h = blockIdx.x >> 7;
    const int n = (blockIdx.x & 127) * 8 + wid;
    const float4* zsrc = reinterpret_cast<const float4*>(z0) + (size_t)n * 64 + lid * 2;
    const float4* wsrc = reinterpret_cast<const float4*>(W)  + (size_t)h * 64 + lid * 2;
    float4 v0 = zsrc[0], v1 = zsrc[1];
    float4 w0 = wsrc[0], w1 = wsrc[1];
    union { __half2 h2[4]; uint4 u; } pk;
    pk.h2[0] = __floats2half2_rn(v0.x * w0.x, v0.y * w0.y);
    pk.h2[1] = __floats2half2_rn(v0.z * w0.z, v0.w * w0.w);
    pk.h2[2] = __floats2half2_rn(v1.x * w1.x, v1.y * w1.y);
    pk.h2[3] = __floats2half2_rn(v1.z * w1.z, v1.w * w1.w);
    const int r = n & 127;
    const int kh = lid >> 4, c = lid & 15;
    g_Yh[(size_t)(((h << 3) + (n >> 7)) * 2 + kh) * 2048 + r * 16 + (c ^ (r & 7))] = pk.u;
}

// ---------------- main kernel ----------------

__global__ void __launch_bounds__(NT, 1)
fc_main_kernel(const float* __restrict__ bias, float* __restrict__ out)
{
    extern __shared__ char smem[];
    const uint32_t smem_base = smem_u32(smem);
    const int tid = threadIdx.x;
    const int wid = tid >> 5;
    const int lid = tid & 31;

    const int h  = (int)(blockIdx.x & 127);
    const int nt = (int)(blockIdx.x >> 7);   // 0..7
    const int n0 = nt << 7;

    // Prologue: B (64KB, both k-halves), A chunk(0), A chunk(1)
    {
        const uint4* gB = g_Yh + (size_t)((h << 3) + nt) * 4096;
        #pragma unroll
        for (int i = 0; i < 8; ++i)
            CP16(smem_base + SM_B + (uint32_t)((tid + i * 512) * 16), gB + tid + i * 512);
        CP_COMMIT();
        #pragma unroll
        for (int g = 0; g < 2; ++g) {
            const uint4* gA = g_z1h + (size_t)g * 4096;
            const uint32_t dst = smem_base + (uint32_t)(g * 65536);
            #pragma unroll
            for (int i = 0; i < 8; ++i)
                CP16(dst + (uint32_t)((tid + i * 512) * 16), gA + tid + i * 512);
            CP_COMMIT();
        }
    }

    const float bv = bias[h];

    // Warp tiling: 4(n) x 4(m); warp tile 32n x 64m.
    const int wn = wid >> 2;    // 0..3
    const int wm = wid & 3;     // 0..3

    const uint32_t e   = (uint32_t)(lid & 7);
    const uint32_t hi  = (uint32_t)(lid >> 4);
    const uint32_t row = (uint32_t)(lid & 15);

    uint32_t a_addr[2];   // operand A rows = n (Yh / B tile)
    #pragma unroll
    for (int mi = 0; mi < 2; ++mi)
        a_addr[mi] = smem_base + SM_B + (uint32_t)((wn * 32 + mi * 16 + row) * 256);
    uint32_t b_addr[4];   // operand B rows = m (z1 / A tile)
    #pragma unroll
    for (int u = 0; u < 4; ++u)
        b_addr[u] = smem_base + (uint32_t)((wm * 64 + u * 16 + row) * 256);

    float acc[2][8][4];
    #pragma unroll
    for (int mi = 0; mi < 2; ++mi)
        #pragma unroll
        for (int j = 0; j < 8; ++j)
            #pragma unroll
            for (int q = 0; q < 4; ++q) acc[mi][j][q] = 0.0f;

    #pragma unroll 1
    for (int g = 0; g < 8; ++g) {         // ms = g>>1 (m-supertile of 256), kh = g&1
        if (g < 7) { CP_WAIT(1); } else { CP_WAIT(0); }
        __syncthreads();

        const uint32_t abuf  = (uint32_t)((g & 1) * 65536);
        const uint32_t khoff = (uint32_t)((g & 1) * 32768);   // B k-half stride

        #pragma unroll
        for (int ks = 0; ks < 8; ++ks) {
            const uint32_t coff = (uint32_t)((((uint32_t)ks * 2u + hi) ^ e) << 4);
            uint32_t fa[2][4], fb[4][4];
            #pragma unroll
            for (int mi = 0; mi < 2; ++mi)
                LDMATRIX_X4(fa[mi][0], fa[mi][1], fa[mi][2], fa[mi][3],
                            a_addr[mi] + khoff + coff);
            #pragma unroll
            for (int u = 0; u < 4; ++u)
                LDMATRIX_X4(fb[u][0], fb[u][1], fb[u][2], fb[u][3],
                            b_addr[u] + abuf + coff);
            #pragma unroll
            for (int mi = 0; mi < 2; ++mi)
                #pragma unroll
                for (int u = 0; u < 4; ++u) {
                    MMA16816(acc[mi][2 * u + 0], fa[mi], fb[u][0], fb[u][2]);
                    MMA16816(acc[mi][2 * u + 1], fa[mi], fb[u][1], fb[u][3]);
                }
        }

        if (g & 1) {
            // Epilogue for m-supertile ms = g>>1 (256 m-cols)
            const int m0 = (g >> 1) << 8;
            const int rr = lid >> 2;
            const int cc = (lid & 3) << 1;
            float* ob = out + (((size_t)h) << 20);
            #pragma unroll
            for (int mi = 0; mi < 2; ++mi) {
                const int ng = n0 + wn * 32 + mi * 16 + rr;
                #pragma unroll
                for (int j = 0; j < 8; ++j) {
                    const int mg = m0 + wm * 64 + j * 8 + cc;
                    float2 v0, v1;
                    v0.x = acc[mi][j][0] + bv; v0.y = acc[mi][j][1] + bv;
                    v1.x = acc[mi][j][2] + bv; v1.y = acc[mi][j][3] + bv;
                    v0.x = (v0.x >= 0.f) ? v0.x : 0.2f * v0.x;
                    v0.y = (v0.y >= 0.f) ? v0.y : 0.2f * v0.y;
                    v1.x = (v1.x >= 0.f) ? v1.x : 0.2f * v1.x;
                    v1.y = (v1.y >= 0.f) ? v1.y : 0.2f * v1.y;
                    __stcs(reinterpret_cast<float2*>(ob + (size_t)ng * 1024 + mg), v0);
                    __stcs(reinterpret_cast<float2*>(ob + (size_t)(ng + 8) * 1024 + mg), v1);
                    acc[mi][j][0] = acc[mi][j][1] = acc[mi][j][2] = acc[mi][j][3] = 0.0f;
                }
            }
        }

        __syncthreads();   // buffer (g&1) fully consumed before refill
        if (g + 2 < 8) {
            const uint4* gA = g_z1h + (size_t)(g + 2) * 4096;
            const uint32_t dst = smem_base + (uint32_t)((g & 1) * 65536);
            #pragma unroll
            for (int i = 0; i < 8; ++i)
                CP16(dst + (uint32_t)((tid + i * 512) * 16), gA + tid + i * 512);
            CP_COMMIT();
        }
    }
}

extern "C" void kernel_launch(void* const* d_in, const int* in_sizes, int n_in,
                              void* d_out, int out_size) {
    const float* z0   = (const float*)d_in[0];   // (1, 1024, 256)
    const float* z1   = (const float*)d_in[1];   // (1, 1024, 256)
    const float* W    = (const float*)d_in[2];   // (128, 256)
    const float* bias = (const float*)d_in[3];   // (128,)
    float* out = (float*)d_out;                  // (1, 128, 1024, 1024)

    prep_z1_kernel<<<128, 256>>>(z1);
    prep_y_kernel<<<16384, 256>>>(z0, W);

    cudaFuncSetAttribute(fc_main_kernel, cudaFuncAttributeMaxDynamicSharedMemorySize, SMEM_BYTES);
    fc_main_kernel<<<1024, NT, SMEM_BYTES>>>(bias, out);
}

// round 6
// speedup vs baseline: 1.4971x; 1.3354x over previous
#include <cuda_runtime.h>
#include <cuda_fp16.h>
#include <cstdint>
#include <cstddef>

// out[h,n,m] = LeakyReLU_{0.2}( sum_d z0[n,d]*z1[m,d]*W[h,d] + bias[h] )
// N=M=1024, D=256, H=128, fp32 in/out.
//
// v6: register-resident GEMM. Per h: out[h] = (z0 o W[h]) @ z1^T.
//  - z1 B-fragments: 128 regs/lane, loaded ONCE (frag-baked g_z1f).
//  - z0 A-fragments: 64 regs/lane, loaded ONCE (frag-baked g_z0f).
//  - Per h, per k-step: A-frags = z0frag * Wfrag (4 HMUL2), W-frags from
//    64KB smem table (broadcast LDS.64). 4 MMAs. NO ldmatrix anywhere.
//  - Mainloop L1 traffic = output stores only.
// CTA = 32n x 128m (8 warps of 16n x 32m), NT=256, grid = 32 nt x 8 ms = 256.

#define NT 256

__device__ uint4 g_z0f[64 * 16 * 32];      // [n16tile][ks][lane] {a0,a1,a2,a3}  512KB
__device__ uint4 g_z1f[128 * 8 * 32];      // [m8tile][kspair][lane] {b0,b1,b0',b1'} 512KB
__device__ uint2 g_wf[128 * 16 * 4];       // [h][ks][c] {w01, w89}              64KB

static constexpr int SMEM_BYTES = 65536;   // W-frag table

__device__ __forceinline__ uint32_t smem_u32(const void* p) {
    uint32_t a;
    asm("{ .reg .u64 t; cvta.to.shared.u64 t, %1; cvt.u32.u64 %0, t; }" : "=r"(a) : "l"(p));
    return a;
}

#define CP16(saddr, gptr)                                                     \
    asm volatile("cp.async.cg.shared.global [%0], [%1], 16;"                  \
                 :: "r"(saddr), "l"(gptr))

#define MMA(c, a0, a1, a2, a3, b0, b1)                                        \
    asm volatile("mma.sync.aligned.m16n8k16.row.col.f32.f16.f16.f32 "         \
                 "{%0,%1,%2,%3}, {%4,%5,%6,%7}, {%8,%9}, {%0,%1,%2,%3};"      \
                 : "+f"((c)[0]), "+f"((c)[1]), "+f"((c)[2]), "+f"((c)[3])     \
                 : "r"(a0), "r"(a1), "r"(a2), "r"(a3), "r"(b0), "r"(b1))

#define HMUL2(d, x, y)                                                        \
    asm("mul.f16x2 %0, %1, %2;" : "=r"(d) : "r"(x), "r"(y))

// ---------------- prep kernels (total ~1.5MB written) ----------------

// A-frag: lane l of tile t_n holds a0=(g,k0),a1=(g+8,k0),a2=(g,k0+8),a3=(g+8,k0+8)
// pairs; g=l>>2, k0=16ks+2(l&3), each reg = {col, col+1}.
__global__ void prep_z0f(const float* __restrict__ z0) {
    int gid = blockIdx.x * 256 + threadIdx.x;      // 32768 threads
    int t_n = gid >> 9, ks = (gid >> 5) & 15, lane = gid & 31;
    int n = t_n * 16 + (lane >> 2);
    int k0 = ks * 16 + (lane & 3) * 2;
    const float* r0 = z0 + (size_t)n * 256;
    const float* r8 = r0 + 8 * 256;
    float2 p0 = *(const float2*)(r0 + k0);
    float2 p1 = *(const float2*)(r8 + k0);
    float2 p2 = *(const float2*)(r0 + k0 + 8);
    float2 p3 = *(const float2*)(r8 + k0 + 8);
    union { __half2 h[4]; uint4 u; } pk;
    pk.h[0] = __floats2half2_rn(p0.x, p0.y);
    pk.h[1] = __floats2half2_rn(p1.x, p1.y);
    pk.h[2] = __floats2half2_rn(p2.x, p2.y);
    pk.h[3] = __floats2half2_rn(p3.x, p3.y);
    g_z0f[gid] = pk.u;
}

// B-frag: lane l of m8-tile t holds b0={(k0,m),(k0+1,m)}, b1={(k0+8,m),(k0+9,m)};
// m = t*8 + (l>>2), k0 = 16ks + 2(l&3). Packed two ks per uint4.
__global__ void prep_z1f(const float* __restrict__ z1) {
    int gid = blockIdx.x * 256 + threadIdx.x;      // 32768 threads
    int t8 = gid >> 8, ksp = (gid >> 5) & 7, lane = gid & 31;
    int m = t8 * 8 + (lane >> 2);
    int ka = ksp * 32 + (lane & 3) * 2;            // ks = 2*ksp
    const float* r = z1 + (size_t)m * 256;
    float2 a0 = *(const float2*)(r + ka);
    float2 a1 = *(const float2*)(r + ka + 8);
    float2 b0 = *(const float2*)(r + ka + 16);     // ks = 2*ksp+1
    float2 b1 = *(const float2*)(r + ka + 24);
    union { __half2 h[4]; uint4 u; } pk;
    pk.h[0] = __floats2half2_rn(a0.x, a0.y);
    pk.h[1] = __floats2half2_rn(a1.x, a1.y);
    pk.h[2] = __floats2half2_rn(b0.x, b0.y);
    pk.h[3] = __floats2half2_rn(b1.x, b1.y);
    g_z1f[gid] = pk.u;
}

// W-frag: per (h, ks, c): {W[h][k0],W[h][k0+1]} and {W[h][k0+8],W[h][k0+9]}.
__global__ void prep_wf(const float* __restrict__ W) {
    int gid = blockIdx.x * 256 + threadIdx.x;      // 8192 threads
    int h = gid >> 6, ks = (gid >> 2) & 15, c = gid & 3;
    int k0 = ks * 16 + c * 2;
    const float* r = W + (size_t)h * 256;
    float2 p0 = *(const float2*)(r + k0);
    float2 p1 = *(const float2*)(r + k0 + 8);
    union { __half2 h2[2]; uint2 u; } pk;
    pk.h2[0] = __floats2half2_rn(p0.x, p0.y);
    pk.h2[1] = __floats2half2_rn(p1.x, p1.y);
    g_wf[gid] = pk.u;
}

// ---------------- main kernel ----------------

__global__ void __launch_bounds__(NT, 1)
fc_main(const float* __restrict__ bias, float* __restrict__ out)
{
    extern __shared__ char smem[];
    const uint32_t sbase = smem_u32(smem);
    const int tid = threadIdx.x;
    const int wid = tid >> 5;
    const int lid = tid & 31;

    const int ms = (int)(blockIdx.x & 7);     // m-supertile (128 m)
    const int nt = (int)(blockIdx.x >> 3);    // n-tile (32 n)
    const int wn = wid >> 2;                  // 0..1  (16n slab)
    const int wm = wid & 3;                   // 0..3  (32m slab)

    // Stage W-frag table (64KB) into smem
    {
        const uint4* gw = reinterpret_cast<const uint4*>(g_wf);
        #pragma unroll
        for (int i = 0; i < 16; ++i)
            CP16(sbase + (uint32_t)((tid + i * 256) * 16), gw + tid + i * 256);
        asm volatile("cp.async.commit_group;" ::: "memory");
    }

    // Load persistent fragments (registers for the whole kernel)
    uint4 z0f[16];
    {
        const uint4* p = g_z0f + ((size_t)(nt * 2 + wn) * 16) * 32 + lid;
        #pragma unroll
        for (int ks = 0; ks < 16; ++ks) z0f[ks] = p[ks * 32];
    }
    uint4 z1p[4][8];
    {
        #pragma unroll
        for (int u = 0; u < 4; ++u) {
            const uint4* p = g_z1f + ((size_t)(ms * 16 + wm * 4 + u) * 8) * 32 + lid;
            #pragma unroll
            for (int kp = 0; kp < 8; ++kp) z1p[u][kp] = p[kp * 32];
        }
    }

    asm volatile("cp.async.wait_group 0;" ::: "memory");
    __syncthreads();

    const uint32_t wlane = sbase + (uint32_t)((lid & 3) * 8);
    const int n_lo = nt * 32 + wn * 16 + (lid >> 2);
    const int mb   = ms * 128 + wm * 32 + (lid & 3) * 2;

    #pragma unroll 1
    for (int h = 0; h < 128; ++h) {
        float acc[4][4];
        #pragma unroll
        for (int u = 0; u < 4; ++u)
            #pragma unroll
            for (int q = 0; q < 4; ++q) acc[u][q] = 0.0f;

        const uint32_t wbase = wlane + (uint32_t)(h * 512);
        #pragma unroll
        for (int ks = 0; ks < 16; ++ks) {
            uint32_t w01, w89;
            asm("ld.shared.v2.b32 {%0,%1}, [%2];"
                : "=r"(w01), "=r"(w89) : "r"(wbase + (uint32_t)(ks * 32)));
            uint32_t a0, a1, a2, a3;
            HMUL2(a0, z0f[ks].x, w01);
            HMUL2(a1, z0f[ks].y, w01);
            HMUL2(a2, z0f[ks].z, w89);
            HMUL2(a3, z0f[ks].w, w89);
            #pragma unroll
            for (int u = 0; u < 4; ++u) {
                const uint32_t b0 = (ks & 1) ? z1p[u][ks >> 1].z : z1p[u][ks >> 1].x;
                const uint32_t b1 = (ks & 1) ? z1p[u][ks >> 1].w : z1p[u][ks >> 1].y;
                MMA(acc[u], a0, a1, a2, a3, b0, b1);
            }
        }

        // Epilogue: bias + LeakyReLU + STG.64
        const float bv = __ldg(bias + h);
        float* ob = out + (((size_t)h) << 20);
        #pragma unroll
        for (int u = 0; u < 4; ++u) {
            const int m = mb + u * 8;
            float2 lo, hi;
            lo.x = acc[u][0] + bv; lo.y = acc[u][1] + bv;
            hi.x = acc[u][2] + bv; hi.y = acc[u][3] + bv;
            lo.x = (lo.x >= 0.f) ? lo.x : 0.2f * lo.x;
            lo.y = (lo.y >= 0.f) ? lo.y : 0.2f * lo.y;
            hi.x = (hi.x >= 0.f) ? hi.x : 0.2f * hi.x;
            hi.y = (hi.y >= 0.f) ? hi.y : 0.2f * hi.y;
            __stcs(reinterpret_cast<float2*>(ob + (size_t)n_lo * 1024 + m), lo);
            __stcs(reinterpret_cast<float2*>(ob + (size_t)(n_lo + 8) * 1024 + m), hi);
        }
    }
}

extern "C" void kernel_launch(void* const* d_in, const int* in_sizes, int n_in,
                              void* d_out, int out_size) {
    const float* z0   = (const float*)d_in[0];   // (1, 1024, 256)
    const float* z1   = (const float*)d_in[1];   // (1, 1024, 256)
    const float* W    = (const float*)d_in[2];   // (128, 256)
    const float* bias = (const float*)d_in[3];   // (128,)
    float* out = (float*)d_out;                  // (1, 128, 1024, 1024)

    prep_z0f<<<128, 256>>>(z0);
    prep_z1f<<<128, 256>>>(z1);
    prep_wf<<<32, 256>>>(W);

    cudaFuncSetAttribute(fc_main, cudaFuncAttributeMaxDynamicSharedMemorySize, SMEM_BYTES);
    fc_main<<<256, NT, SMEM_BYTES>>>(bias, out);
}

// round 7
// speedup vs baseline: 1.5231x; 1.0174x over previous
#include <cuda_runtime.h>
#include <cuda_fp16.h>
#include <cstdint>
#include <cstddef>

// out[h,n,m] = LeakyReLU_{0.2}( sum_d z0[n,d]*z1[m,d]*W[h,d] + bias[h] )
// N=M=1024, D=256, H=128, fp32 in/out.
//
// v7: register-resident GEMM (v6 engine) + occupancy/stagger fixes.
//  - CTA = 16n x 128m, NT=128 (4 warps, warp tile 16n x 32m), grid 512,
//    2 CTAs/SM -> finer wave granularity + natural desync.
//  - Per-warp h-stagger so epilogue bursts never align on an SMSP.
//  - Explicit W-frag LDS prefetch ring; bias staged in smem.

#define NT 128

__device__ uint4 g_z0f[64 * 16 * 32];      // [n16tile][ks][lane] {a0,a1,a2,a3}  512KB
__device__ uint4 g_z1f[128 * 8 * 32];      // [m8tile][kspair][lane]             512KB
__device__ uint2 g_wf[128 * 16 * 4];       // [h][ks][c] {w01, w89}              64KB

static constexpr int SM_BIAS = 65536;
static constexpr int SMEM_BYTES = 65536 + 512;

__device__ __forceinline__ uint32_t smem_u32(const void* p) {
    uint32_t a;
    asm("{ .reg .u64 t; cvta.to.shared.u64 t, %1; cvt.u32.u64 %0, t; }" : "=r"(a) : "l"(p));
    return a;
}

#define CP16(saddr, gptr)                                                     \
    asm volatile("cp.async.cg.shared.global [%0], [%1], 16;"                  \
                 :: "r"(saddr), "l"(gptr))

#define MMA(c, a0, a1, a2, a3, b0, b1)                                        \
    asm volatile("mma.sync.aligned.m16n8k16.row.col.f32.f16.f16.f32 "         \
                 "{%0,%1,%2,%3}, {%4,%5,%6,%7}, {%8,%9}, {%0,%1,%2,%3};"      \
                 : "+f"((c)[0]), "+f"((c)[1]), "+f"((c)[2]), "+f"((c)[3])     \
                 : "r"(a0), "r"(a1), "r"(a2), "r"(a3), "r"(b0), "r"(b1))

#define HMUL2(d, x, y)                                                        \
    asm("mul.f16x2 %0, %1, %2;" : "=r"(d) : "r"(x), "r"(y))

#define LDS_W(w0, w1, addr)                                                   \
    asm("ld.shared.v2.b32 {%0,%1}, [%2];" : "=r"(w0), "=r"(w1) : "r"(addr))

// ---------------- prep kernels ----------------

__global__ void prep_z0f(const float* __restrict__ z0) {
    int gid = blockIdx.x * 256 + threadIdx.x;      // 32768 threads
    int t_n = gid >> 9, ks = (gid >> 5) & 15, lane = gid & 31;
    int n = t_n * 16 + (lane >> 2);
    int k0 = ks * 16 + (lane & 3) * 2;
    const float* r0 = z0 + (size_t)n * 256;
    const float* r8 = r0 + 8 * 256;
    float2 p0 = *(const float2*)(r0 + k0);
    float2 p1 = *(const float2*)(r8 + k0);
    float2 p2 = *(const float2*)(r0 + k0 + 8);
    float2 p3 = *(const float2*)(r8 + k0 + 8);
    union { __half2 h[4]; uint4 u; } pk;
    pk.h[0] = __floats2half2_rn(p0.x, p0.y);
    pk.h[1] = __floats2half2_rn(p1.x, p1.y);
    pk.h[2] = __floats2half2_rn(p2.x, p2.y);
    pk.h[3] = __floats2half2_rn(p3.x, p3.y);
    g_z0f[gid] = pk.u;
}

__global__ void prep_z1f(const float* __restrict__ z1) {
    int gid = blockIdx.x * 256 + threadIdx.x;      // 32768 threads
    int t8 = gid >> 8, ksp = (gid >> 5) & 7, lane = gid & 31;
    int m = t8 * 8 + (lane >> 2);
    int ka = ksp * 32 + (lane & 3) * 2;
    const float* r = z1 + (size_t)m * 256;
    float2 a0 = *(const float2*)(r + ka);
    float2 a1 = *(const float2*)(r + ka + 8);
    float2 b0 = *(const float2*)(r + ka + 16);
    float2 b1 = *(const float2*)(r + ka + 24);
    union { __half2 h[4]; uint4 u; } pk;
    pk.h[0] = __floats2half2_rn(a0.x, a0.y);
    pk.h[1] = __floats2half2_rn(a1.x, a1.y);
    pk.h[2] = __floats2half2_rn(b0.x, b0.y);
    pk.h[3] = __floats2half2_rn(b1.x, b1.y);
    g_z1f[gid] = pk.u;
}

__global__ void prep_wf(const float* __restrict__ W) {
    int gid = blockIdx.x * 256 + threadIdx.x;      // 8192 threads
    int h = gid >> 6, ks = (gid >> 2) & 15, c = gid & 3;
    int k0 = ks * 16 + c * 2;
    const float* r = W + (size_t)h * 256;
    float2 p0 = *(const float2*)(r + k0);
    float2 p1 = *(const float2*)(r + k0 + 8);
    union { __half2 h2[2]; uint2 u; } pk;
    pk.h2[0] = __floats2half2_rn(p0.x, p0.y);
    pk.h2[1] = __floats2half2_rn(p1.x, p1.y);
    g_wf[gid] = pk.u;
}

// ---------------- main kernel ----------------

__global__ void __launch_bounds__(NT, 2)
fc_main(const float* __restrict__ bias, float* __restrict__ out)
{
    extern __shared__ char smem[];
    const uint32_t sbase = smem_u32(smem);
    const int tid = threadIdx.x;
    const int wid = tid >> 5;      // 0..3
    const int lid = tid & 31;

    const int ms = (int)(blockIdx.x & 7);     // m-supertile (128 m)
    const int nt = (int)(blockIdx.x >> 3);    // n-tile (16 n), 0..63
    const int wm = wid;                       // 32m slab per warp

    // Stage W-frag table (64KB) + bias (512B) into smem
    {
        const uint4* gw = reinterpret_cast<const uint4*>(g_wf);
        #pragma unroll
        for (int i = 0; i < 32; ++i)
            CP16(sbase + (uint32_t)((tid + i * 128) * 16), gw + tid + i * 128);
        if (tid < 32)
            CP16(sbase + SM_BIAS + (uint32_t)(tid * 16),
                 reinterpret_cast<const uint4*>(bias) + tid);
        asm volatile("cp.async.commit_group;" ::: "memory");
    }

    // Persistent fragments
    uint4 z0f[16];
    {
        const uint4* p = g_z0f + ((size_t)nt * 16) * 32 + lid;
        #pragma unroll
        for (int ks = 0; ks < 16; ++ks) z0f[ks] = p[ks * 32];
    }
    uint4 z1p[4][8];
    {
        #pragma unroll
        for (int u = 0; u < 4; ++u) {
            const uint4* p = g_z1f + ((size_t)(ms * 16 + wm * 4 + u) * 8) * 32 + lid;
            #pragma unroll
            for (int kp = 0; kp < 8; ++kp) z1p[u][kp] = p[kp * 32];
        }
    }

    asm volatile("cp.async.wait_group 0;" ::: "memory");
    __syncthreads();

    const uint32_t wlane = sbase + (uint32_t)((lid & 3) * 8);
    const int n_lo = nt * 16 + (lid >> 2);
    const int mb   = ms * 128 + wm * 32 + (lid & 3) * 2;

    // Per-warp h-stagger: desync epilogue bursts across warps/CTAs.
    const int hb = (((int)blockIdx.x << 5) + (wid << 3)) & 127;

    #pragma unroll 1
    for (int i = 0; i < 128; ++i) {
        const int h = (i + hb) & 127;

        float acc[4][4];
        #pragma unroll
        for (int u = 0; u < 4; ++u)
            #pragma unroll
            for (int q = 0; q < 4; ++q) acc[u][q] = 0.0f;

        const uint32_t wbase = wlane + (uint32_t)(h * 512);

        uint32_t wc0, wc1;
        LDS_W(wc0, wc1, wbase);
        #pragma unroll
        for (int ks = 0; ks < 16; ++ks) {
            uint32_t wn0 = wc0, wn1 = wc1;
            if (ks < 15)
                LDS_W(wn0, wn1, wbase + (uint32_t)((ks + 1) * 32));
            uint32_t a0, a1, a2, a3;
            HMUL2(a0, z0f[ks].x, wc0);
            HMUL2(a1, z0f[ks].y, wc0);
            HMUL2(a2, z0f[ks].z, wc1);
            HMUL2(a3, z0f[ks].w, wc1);
            #pragma unroll
            for (int u = 0; u < 4; ++u) {
                const uint32_t b0 = (ks & 1) ? z1p[u][ks >> 1].z : z1p[u][ks >> 1].x;
                const uint32_t b1 = (ks & 1) ? z1p[u][ks >> 1].w : z1p[u][ks >> 1].y;
                MMA(acc[u], a0, a1, a2, a3, b0, b1);
            }
            wc0 = wn0; wc1 = wn1;
        }

        // Epilogue: bias + LeakyReLU + STG.64 streaming
        float bv;
        asm("ld.shared.f32 %0, [%1];" : "=f"(bv) : "r"(sbase + SM_BIAS + (uint32_t)(h * 4)));
        float* ob = out + (((size_t)h) << 20);
        #pragma unroll
        for (int u = 0; u < 4; ++u) {
            const int m = mb + u * 8;
            float2 lo, hi;
            lo.x = acc[u][0] + bv; lo.y = acc[u][1] + bv;
            hi.x = acc[u][2] + bv; hi.y = acc[u][3] + bv;
            lo.x = (lo.x >= 0.f) ? lo.x : 0.2f * lo.x;
            lo.y = (lo.y >= 0.f) ? lo.y : 0.2f * lo.y;
            hi.x = (hi.x >= 0.f) ? hi.x : 0.2f * hi.x;
            hi.y = (hi.y >= 0.f) ? hi.y : 0.2f * hi.y;
            __stcs(reinterpret_cast<float2*>(ob + (size_t)n_lo * 1024 + m), lo);
            __stcs(reinterpret_cast<float2*>(ob + (size_t)(n_lo + 8) * 1024 + m), hi);
        }
    }
}

extern "C" void kernel_launch(void* const* d_in, const int* in_sizes, int n_in,
                              void* d_out, int out_size) {
    const float* z0   = (const float*)d_in[0];   // (1, 1024, 256)
    const float* z1   = (const float*)d_in[1];   // (1, 1024, 256)
    const float* W    = (const float*)d_in[2];   // (128, 256)
    const float* bias = (const float*)d_in[3];   // (128,)
    float* out = (float*)d_out;                  // (1, 128, 1024, 1024)

    prep_z0f<<<128, 256>>>(z0);
    prep_z1f<<<128, 256>>>(z1);
    prep_wf<<<32, 256>>>(W);

    cudaFuncSetAttribute(fc_main, cudaFuncAttributeMaxDynamicSharedMemorySize, SMEM_BYTES);
    fc_main<<<512, NT, SMEM_BYTES>>>(bias, out);
}